// round 4
// baseline (speedup 1.0000x reference)
#include <cuda_runtime.h>
#include <cuda_bf16.h>
#include <cstdint>

#define BB 32768
#define FF 128
#define HH 64
#define THREADS 256
#define WARPS 8
#define ROWS_PER_CTA 1024
#define ROWS_STEP 32
#define NCHUNK (BB / ROWS_PER_CTA)    // 32
#define STEPS (ROWS_PER_CTA / ROWS_STEP)  // 32
#define H1S 72                        // bf16 elems per row (144B stride)

// ---- device scratch (no cudaMalloc allowed) ----
__device__ __align__(16) uint32_t g_bfragH[FF * 2048];   // per-lane packed B frags (hi)
__device__ __align__(16) uint32_t g_bfragL[FF * 2048];   // (lo)
__device__ float g_contrib[FF * BB];

__device__ __forceinline__ uint32_t pack_bf16(float v0, float v1) {
    uint32_t r;
    asm("cvt.rn.bf16x2.f32 %0, %1, %2;" : "=r"(r) : "f"(v1), "f"(v0));
    return r;
}
__device__ __forceinline__ uint32_t smem_u32(const void* p) {
    uint32_t a;
    asm("{ .reg .u64 t; cvta.to.shared.u64 t, %1; cvt.u32.u64 %0, t; }" : "=r"(a) : "l"(p));
    return a;
}
__device__ __forceinline__ void mma16816(float* d,
                                         uint32_t a0, uint32_t a1, uint32_t a2, uint32_t a3,
                                         uint32_t b0, uint32_t b1) {
    asm volatile(
        "mma.sync.aligned.m16n8k16.row.col.f32.bf16.bf16.f32 "
        "{%0,%1,%2,%3}, {%4,%5,%6,%7}, {%8,%9}, {%0,%1,%2,%3};"
        : "+f"(d[0]), "+f"(d[1]), "+f"(d[2]), "+f"(d[3])
        : "r"(a0), "r"(a1), "r"(a2), "r"(a3), "r"(b0), "r"(b1));
}
__device__ __forceinline__ void ldsm4(uint32_t& r0, uint32_t& r1, uint32_t& r2, uint32_t& r3,
                                      uint32_t addr) {
    asm volatile("ldmatrix.sync.aligned.m8n8.x4.shared.b16 {%0,%1,%2,%3}, [%4];"
                 : "=r"(r0), "=r"(r1), "=r"(r2), "=r"(r3) : "r"(addr));
}
__device__ __forceinline__ void sts128(uint32_t addr, uint32_t r0, uint32_t r1,
                                       uint32_t r2, uint32_t r3) {
    asm volatile("st.shared.v4.b32 [%0], {%1,%2,%3,%4};"
                 :: "r"(addr), "r"(r0), "r"(r1), "r"(r2), "r"(r3) : "memory");
}

// -------- prep: split w2 into bf16 hi/lo packed in m16n8k16 B-fragment order --------
__global__ void prep_kernel(const float* __restrict__ w2) {
    int e = blockIdx.x * blockDim.x + threadIdx.x;   // < FF*2048
    int lane = e & 31;
    int i = (e >> 5) & 1;
    int q = (e >> 6) & 3;
    int w = (e >> 8) & 7;
    int f = e >> 11;
    int k0 = q * 16 + (lane & 3) * 2 + 8 * i;
    int g = w * 8 + (lane >> 2);
    float v0 = w2[f * 4096 + k0 * 64 + g];
    float v1 = w2[f * 4096 + (k0 + 1) * 64 + g];
    uint32_t hi = pack_bf16(v0, v1);
    float r0 = v0 - __uint_as_float(hi << 16);
    float r1 = v1 - __uint_as_float(hi & 0xFFFF0000u);
    g_bfragH[e] = hi;
    g_bfragL[e] = pack_bf16(r0, r1);
}

// -------- main kernel --------
__global__ __launch_bounds__(THREADS)
void mlp_mma_kernel(const float* __restrict__ x,
                    const float* __restrict__ w1,
                    const float* __restrict__ b1,
                    const float* __restrict__ b2,
                    const float* __restrict__ w3,
                    const float* __restrict__ b3) {
    __shared__ __align__(16) __nv_bfloat16 h1h[ROWS_STEP * H1S];
    __shared__ __align__(16) __nv_bfloat16 h1l[ROWS_STEP * H1S];
    __shared__ float wsum[WARPS][ROWS_STEP];
    __shared__ float w1s[HH], b1s[HH], b2s[HH], w3s[HH];

    const int tid = threadIdx.x;
    const int warp = tid >> 5, lane = tid & 31;
    const int f = blockIdx.y;
    const int row0 = blockIdx.x * ROWS_PER_CTA;

    if (tid < HH) {
        w1s[tid] = w1[f * HH + tid];
        b1s[tid] = b1[f * HH + tid];
        b2s[tid] = b2[f * HH + tid];
        w3s[tid] = w3[f * HH + tid];
    }
    const float b3f = __ldg(b3 + f);

    // B fragments in registers for the whole CTA (warp owns n-slice warp*8..+8)
    uint32_t bh[4][2], bl[4][2];
    {
        int base = f * 2048 + warp * 256 + lane;
        #pragma unroll
        for (int q = 0; q < 4; ++q)
            #pragma unroll
            for (int i = 0; i < 2; ++i) {
                bh[q][i] = g_bfragH[base + q * 64 + i * 32];
                bl[q][i] = g_bfragL[base + q * 64 + i * 32];
            }
    }

    const int m = lane >> 2, c = lane & 3;
    const int n0 = warp * 8 + 2 * c;
    const int hr = tid >> 3;              // 0..31 : h1 row this thread fills
    const int hcb = (tid & 7) * 16;       // byte col base (8 bf16 = 16B)

    const uint32_t h1h_b = smem_u32(h1h);
    const uint32_t h1l_b = smem_u32(h1l);
    // ldmatrix per-lane offset: row = (lane&7) + ((lane>>3)&1)*8 ; kbyte = (lane>>4)*16
    const uint32_t lmoff = (uint32_t)(((lane & 7) + ((lane >> 3) & 1) * 8) * (H1S * 2)
                                      + (lane >> 4) * 16);
    const uint32_t st_h = h1h_b + (uint32_t)(hr * (H1S * 2) + hcb);
    const uint32_t st_l = h1l_b + (uint32_t)(hr * (H1S * 2) + hcb);

    __syncthreads();   // weight smem ready

    float xv = __ldg(x + (size_t)(row0 + hr) * FF + f);

    for (int stp = 0; stp < STEPS; ++stp) {
        const int rbase = row0 + stp * ROWS_STEP;

        // ---- layer 1 for 32 rows: h1 = relu(x*w1+b1), bf16 hi/lo split ----
        {
            const int hc = (tid & 7) * 8;
            float4 wa = *(const float4*)(w1s + hc);
            float4 wb = *(const float4*)(w1s + hc + 4);
            float4 ba = *(const float4*)(b1s + hc);
            float4 bb = *(const float4*)(b1s + hc + 4);
            float v0 = fmaxf(fmaf(xv, wa.x, ba.x), 0.f);
            float v1 = fmaxf(fmaf(xv, wa.y, ba.y), 0.f);
            float v2 = fmaxf(fmaf(xv, wa.z, ba.z), 0.f);
            float v3 = fmaxf(fmaf(xv, wa.w, ba.w), 0.f);
            float v4 = fmaxf(fmaf(xv, wb.x, bb.x), 0.f);
            float v5 = fmaxf(fmaf(xv, wb.y, bb.y), 0.f);
            float v6 = fmaxf(fmaf(xv, wb.z, bb.z), 0.f);
            float v7 = fmaxf(fmaf(xv, wb.w, bb.w), 0.f);
            uint32_t h0 = pack_bf16(v0, v1), h1v = pack_bf16(v2, v3);
            uint32_t h2 = pack_bf16(v4, v5), h3 = pack_bf16(v6, v7);
            uint32_t l0 = pack_bf16(v0 - __uint_as_float(h0 << 16),
                                    v1 - __uint_as_float(h0 & 0xFFFF0000u));
            uint32_t l1 = pack_bf16(v2 - __uint_as_float(h1v << 16),
                                    v3 - __uint_as_float(h1v & 0xFFFF0000u));
            uint32_t l2 = pack_bf16(v4 - __uint_as_float(h2 << 16),
                                    v5 - __uint_as_float(h2 & 0xFFFF0000u));
            uint32_t l3 = pack_bf16(v6 - __uint_as_float(h3 << 16),
                                    v7 - __uint_as_float(h3 & 0xFFFF0000u));
            sts128(st_h, h0, h1v, h2, h3);
            sts128(st_l, l0, l1, l2, l3);
        }

        // prefetch next step's x before the barrier (hidden behind MMAs)
        if (stp + 1 < STEPS)
            xv = __ldg(x + (size_t)(rbase + ROWS_STEP + hr) * FF + f);

        __syncthreads();   // (A) h1 visible; prev wsum consumers done

        // ---- grouped GEMM: 2 M-tiles x 3-pass bf16-split MMA ----
        float d[2][4] = {{0.f, 0.f, 0.f, 0.f}, {0.f, 0.f, 0.f, 0.f}};
        #pragma unroll
        for (int t = 0; t < 2; ++t) {
            const uint32_t tbh = h1h_b + lmoff + (uint32_t)(t * 16 * H1S * 2);
            const uint32_t tbl = h1l_b + lmoff + (uint32_t)(t * 16 * H1S * 2);
            #pragma unroll
            for (int q = 0; q < 4; ++q) {
                uint32_t a0, a1, a2, a3, c0, c1, c2, c3;
                ldsm4(a0, a1, a2, a3, tbh + q * 32);
                ldsm4(c0, c1, c2, c3, tbl + q * 32);
                mma16816(d[t], a0, a1, a2, a3, bh[q][0], bh[q][1]);
                mma16816(d[t], a0, a1, a2, a3, bl[q][0], bl[q][1]);
                mma16816(d[t], c0, c1, c2, c3, bh[q][0], bh[q][1]);
            }
        }

        // ---- epilogue: relu(D + b2) . w3, quad-reduce -> per-row sums ----
        {
            float B0 = b2s[n0], B1 = b2s[n0 + 1];
            float W0 = w3s[n0], W1 = w3s[n0 + 1];
            #pragma unroll
            for (int t = 0; t < 2; ++t) {
                float e0 = fmaf(fmaxf(d[t][0] + B0, 0.f), W0, fmaxf(d[t][1] + B1, 0.f) * W1);
                float e1 = fmaf(fmaxf(d[t][2] + B0, 0.f), W0, fmaxf(d[t][3] + B1, 0.f) * W1);
                e0 += __shfl_xor_sync(0xFFFFFFFFu, e0, 1);
                e0 += __shfl_xor_sync(0xFFFFFFFFu, e0, 2);
                e1 += __shfl_xor_sync(0xFFFFFFFFu, e1, 1);
                e1 += __shfl_xor_sync(0xFFFFFFFFu, e1, 2);
                if (c == 0) {
                    wsum[warp][t * 16 + m] = e0;
                    wsum[warp][t * 16 + 8 + m] = e1;
                }
            }
        }
        __syncthreads();   // (B) wsum visible; h1 fully consumed

        if (tid < ROWS_STEP) {
            float s = ((wsum[0][tid] + wsum[1][tid]) + (wsum[2][tid] + wsum[3][tid])) +
                      ((wsum[4][tid] + wsum[5][tid]) + (wsum[6][tid] + wsum[7][tid]));
            g_contrib[f * BB + rbase + tid] = s + b3f;
        }
        // next iteration's barrier (A) protects wsum rewrite
    }
}

__global__ void finalize_kernel(const float* __restrict__ bias,
                                float* __restrict__ out) {
    int b = blockIdx.x * blockDim.x + threadIdx.x;
    if (b >= BB) return;
    float l = bias[0];
    #pragma unroll 16
    for (int f = 0; f < FF; ++f) l += g_contrib[f * BB + b];
    float p = 1.0f / (1.0f + expf(-l));
    out[2 * b + 0] = 1.0f - p;
    out[2 * b + 1] = p;
}

extern "C" void kernel_launch(void* const* d_in, const int* in_sizes, int n_in,
                              void* d_out, int out_size) {
    const float* x    = (const float*)d_in[0];
    const float* w1   = (const float*)d_in[1];
    const float* b1   = (const float*)d_in[2];
    const float* w2   = (const float*)d_in[3];
    const float* b2   = (const float*)d_in[4];
    const float* w3   = (const float*)d_in[5];
    const float* b3   = (const float*)d_in[6];
    const float* bias = (const float*)d_in[7];
    float* out = (float*)d_out;

    prep_kernel<<<(FF * 2048) / 256, 256>>>(w2);
    dim3 grid(NCHUNK, FF);   // 32 x 128 = 4096 CTAs
    mlp_mma_kernel<<<grid, THREADS>>>(x, w1, b1, b2, w3, b3);
    finalize_kernel<<<BB / 256, 256>>>(bias, out);
}

// round 5
// speedup vs baseline: 1.2791x; 1.2791x over previous
#include <cuda_runtime.h>
#include <cuda_bf16.h>
#include <cstdint>

#define BB 32768
#define FF 128
#define HH 64
#define THREADS 256
#define WARPS 8
#define ROWS_PER_CTA 1024
#define ROWS_STEP 32
#define NCHUNK (BB / ROWS_PER_CTA)        // 32
#define STEPS (ROWS_PER_CTA / ROWS_STEP)  // 32
#define H1S 72                            // bf16 elems per row (144B stride)

// ---- device scratch (no cudaMalloc allowed) ----
__device__ __align__(16) uint32_t g_bfragH[FF * 2048];
__device__ __align__(16) uint32_t g_bfragL[FF * 2048];
__device__ float g_contrib[FF * BB];

__device__ __forceinline__ uint32_t pack_bf16(float v0, float v1) {
    uint32_t r;
    asm("cvt.rn.bf16x2.f32 %0, %1, %2;" : "=r"(r) : "f"(v1), "f"(v0));
    return r;
}
__device__ __forceinline__ uint32_t smem_u32(const void* p) {
    uint32_t a;
    asm("{ .reg .u64 t; cvta.to.shared.u64 t, %1; cvt.u32.u64 %0, t; }" : "=r"(a) : "l"(p));
    return a;
}
__device__ __forceinline__ void mma16816(float* d,
                                         uint32_t a0, uint32_t a1, uint32_t a2, uint32_t a3,
                                         uint32_t b0, uint32_t b1) {
    asm volatile(
        "mma.sync.aligned.m16n8k16.row.col.f32.bf16.bf16.f32 "
        "{%0,%1,%2,%3}, {%4,%5,%6,%7}, {%8,%9}, {%0,%1,%2,%3};"
        : "+f"(d[0]), "+f"(d[1]), "+f"(d[2]), "+f"(d[3])
        : "r"(a0), "r"(a1), "r"(a2), "r"(a3), "r"(b0), "r"(b1));
}
__device__ __forceinline__ void ldsm4(uint32_t& r0, uint32_t& r1, uint32_t& r2, uint32_t& r3,
                                      uint32_t addr) {
    asm volatile("ldmatrix.sync.aligned.m8n8.x4.shared.b16 {%0,%1,%2,%3}, [%4];"
                 : "=r"(r0), "=r"(r1), "=r"(r2), "=r"(r3) : "r"(addr));
}
__device__ __forceinline__ void sts128(uint32_t addr, uint32_t r0, uint32_t r1,
                                       uint32_t r2, uint32_t r3) {
    asm volatile("st.shared.v4.b32 [%0], {%1,%2,%3,%4};"
                 :: "r"(addr), "r"(r0), "r"(r1), "r"(r2), "r"(r3) : "memory");
}

// -------- prep: split w2 into bf16 hi/lo packed in m16n8k16 B-fragment order --------
__global__ void prep_kernel(const float* __restrict__ w2) {
    int e = blockIdx.x * blockDim.x + threadIdx.x;   // < FF*2048
    int lane = e & 31;
    int i = (e >> 5) & 1;
    int q = (e >> 6) & 3;
    int w = (e >> 8) & 7;
    int f = e >> 11;
    int k0 = q * 16 + (lane & 3) * 2 + 8 * i;
    int g = w * 8 + (lane >> 2);
    float v0 = w2[f * 4096 + k0 * 64 + g];
    float v1 = w2[f * 4096 + (k0 + 1) * 64 + g];
    uint32_t hi = pack_bf16(v0, v1);
    float r0 = v0 - __uint_as_float(hi << 16);
    float r1 = v1 - __uint_as_float(hi & 0xFFFF0000u);
    g_bfragH[e] = hi;
    g_bfragL[e] = pack_bf16(r0, r1);
}

// -------- main kernel (software-pipelined, 1 barrier/step) --------
__global__ __launch_bounds__(THREADS)
void mlp_mma_kernel(const float* __restrict__ x,
                    const float* __restrict__ w1,
                    const float* __restrict__ b1,
                    const float* __restrict__ b2,
                    const float* __restrict__ w3,
                    const float* __restrict__ b3) {
    __shared__ __align__(16) __nv_bfloat16 h1h[2][ROWS_STEP * H1S];
    __shared__ __align__(16) __nv_bfloat16 h1l[2][ROWS_STEP * H1S];
    __shared__ float wsum[2][WARPS][ROWS_STEP];
    __shared__ float w1s[HH], b1s[HH], b2s[HH], w3s[HH];

    const int tid = threadIdx.x;
    const int warp = tid >> 5, lane = tid & 31;
    const int f = blockIdx.y;
    const int row0 = blockIdx.x * ROWS_PER_CTA;

    if (tid < HH) {
        w1s[tid] = w1[f * HH + tid];
        b1s[tid] = b1[f * HH + tid];
        b2s[tid] = b2[f * HH + tid];
        w3s[tid] = w3[f * HH + tid];
    }
    const float b3f = __ldg(b3 + f);

    // B fragments in registers for the whole CTA (warp owns n-slice warp*8..+8)
    uint32_t bh[4][2], bl[4][2];
    {
        int base = f * 2048 + warp * 256 + lane;
        #pragma unroll
        for (int q = 0; q < 4; ++q)
            #pragma unroll
            for (int i = 0; i < 2; ++i) {
                bh[q][i] = g_bfragH[base + q * 64 + i * 32];
                bl[q][i] = g_bfragL[base + q * 64 + i * 32];
            }
    }

    const int m = lane >> 2, c = lane & 3;
    const int n0 = warp * 8 + 2 * c;
    const int hr = tid >> 3;              // 0..31 : h1 row this thread fills
    const int hcb = (tid & 7) * 16;       // byte col base (8 bf16 = 16B)
    const int hc = (tid & 7) * 8;

    const uint32_t bufH[2] = {smem_u32(h1h[0]), smem_u32(h1h[1])};
    const uint32_t bufL[2] = {smem_u32(h1l[0]), smem_u32(h1l[1])};
    const uint32_t lmoff = (uint32_t)(((lane & 7) + ((lane >> 3) & 1) * 8) * (H1S * 2)
                                      + (lane >> 4) * 16);
    const uint32_t stoff = (uint32_t)(hr * (H1S * 2) + hcb);

    // weight vectors for this thread's 8 h-values (loop-invariant)
    __syncthreads();
    const float4 wa = *(const float4*)(w1s + hc);
    const float4 wb = *(const float4*)(w1s + hc + 4);
    const float4 ba = *(const float4*)(b1s + hc);
    const float4 bb = *(const float4*)(b1s + hc + 4);

    // ---- layer-1 compute + bf16 split + STS (for step whose x is xv) ----
    auto h1_store = [&](float xv, int buf) {
        float v0 = fmaxf(fmaf(xv, wa.x, ba.x), 0.f);
        float v1 = fmaxf(fmaf(xv, wa.y, ba.y), 0.f);
        float v2 = fmaxf(fmaf(xv, wa.z, ba.z), 0.f);
        float v3 = fmaxf(fmaf(xv, wa.w, ba.w), 0.f);
        float v4 = fmaxf(fmaf(xv, wb.x, bb.x), 0.f);
        float v5 = fmaxf(fmaf(xv, wb.y, bb.y), 0.f);
        float v6 = fmaxf(fmaf(xv, wb.z, bb.z), 0.f);
        float v7 = fmaxf(fmaf(xv, wb.w, bb.w), 0.f);
        uint32_t h0 = pack_bf16(v0, v1), h1v = pack_bf16(v2, v3);
        uint32_t h2 = pack_bf16(v4, v5), h3 = pack_bf16(v6, v7);
        uint32_t l0 = pack_bf16(v0 - __uint_as_float(h0 << 16),
                                v1 - __uint_as_float(h0 & 0xFFFF0000u));
        uint32_t l1 = pack_bf16(v2 - __uint_as_float(h1v << 16),
                                v3 - __uint_as_float(h1v & 0xFFFF0000u));
        uint32_t l2 = pack_bf16(v4 - __uint_as_float(h2 << 16),
                                v5 - __uint_as_float(h2 & 0xFFFF0000u));
        uint32_t l3 = pack_bf16(v6 - __uint_as_float(h3 << 16),
                                v7 - __uint_as_float(h3 & 0xFFFF0000u));
        sts128(bufH[buf] + stoff, h0, h1v, h2, h3);
        sts128(bufL[buf] + stoff, l0, l1, l2, l3);
    };

    // prologue: h1(0) into buf0; prefetch x for step 1
    float xv0 = __ldg(x + (size_t)(row0 + hr) * FF + f);
    h1_store(xv0, 0);
    float xv1 = __ldg(x + (size_t)(row0 + ROWS_STEP + hr) * FF + f);
    __syncthreads();

    for (int stp = 0; stp < STEPS; ++stp) {
        const int cur = stp & 1;

        // (a) previous step's contrib write (independent, overlaps everything)
        if (stp > 0 && tid < ROWS_STEP) {
            const float* ws = &wsum[cur ^ 1][0][tid];
            float s = ((ws[0] + ws[ROWS_STEP]) + (ws[2 * ROWS_STEP] + ws[3 * ROWS_STEP])) +
                      ((ws[4 * ROWS_STEP] + ws[5 * ROWS_STEP]) +
                       (ws[6 * ROWS_STEP] + ws[7 * ROWS_STEP]));
            g_contrib[f * BB + row0 + (stp - 1) * ROWS_STEP + tid] = s + b3f;
        }

        // (b) next step's layer-1 + STS into the other buffer (independent of MMAs)
        if (stp + 1 < STEPS) {
            h1_store(xv1, cur ^ 1);
            if (stp + 2 < STEPS)
                xv1 = __ldg(x + (size_t)(row0 + (stp + 2) * ROWS_STEP + hr) * FF + f);
        }

        // (c) MMA block on current buffer (LDSM interleaved)
        float d[2][4] = {{0.f, 0.f, 0.f, 0.f}, {0.f, 0.f, 0.f, 0.f}};
        #pragma unroll
        for (int t = 0; t < 2; ++t) {
            const uint32_t tbh = bufH[cur] + lmoff + (uint32_t)(t * 16 * H1S * 2);
            const uint32_t tbl = bufL[cur] + lmoff + (uint32_t)(t * 16 * H1S * 2);
            #pragma unroll
            for (int q = 0; q < 4; ++q) {
                uint32_t a0, a1, a2, a3, c0, c1, c2, c3;
                ldsm4(a0, a1, a2, a3, tbh + q * 32);
                ldsm4(c0, c1, c2, c3, tbl + q * 32);
                mma16816(d[t], a0, a1, a2, a3, bh[q][0], bh[q][1]);
                mma16816(d[t], a0, a1, a2, a3, bl[q][0], bl[q][1]);
                mma16816(d[t], c0, c1, c2, c3, bh[q][0], bh[q][1]);
            }
        }

        // (d) epilogue: relu(D + b2) . w3, quad-reduce -> wsum[cur]
        {
            float B0 = b2s[n0], B1 = b2s[n0 + 1];
            float W0 = w3s[n0], W1 = w3s[n0 + 1];
            #pragma unroll
            for (int t = 0; t < 2; ++t) {
                float e0 = fmaf(fmaxf(d[t][0] + B0, 0.f), W0, fmaxf(d[t][1] + B1, 0.f) * W1);
                float e1 = fmaf(fmaxf(d[t][2] + B0, 0.f), W0, fmaxf(d[t][3] + B1, 0.f) * W1);
                e0 += __shfl_xor_sync(0xFFFFFFFFu, e0, 1);
                e0 += __shfl_xor_sync(0xFFFFFFFFu, e0, 2);
                e1 += __shfl_xor_sync(0xFFFFFFFFu, e1, 1);
                e1 += __shfl_xor_sync(0xFFFFFFFFu, e1, 2);
                if (c == 0) {
                    wsum[cur][warp][t * 16 + m] = e0;
                    wsum[cur][warp][t * 16 + 8 + m] = e1;
                }
            }
        }

        // (e) single barrier: publishes this step's wsum AND next buffer's h1
        __syncthreads();
    }

    // tail: contrib for last step
    if (tid < ROWS_STEP) {
        const float* ws = &wsum[(STEPS - 1) & 1][0][tid];
        float s = ((ws[0] + ws[ROWS_STEP]) + (ws[2 * ROWS_STEP] + ws[3 * ROWS_STEP])) +
                  ((ws[4 * ROWS_STEP] + ws[5 * ROWS_STEP]) +
                   (ws[6 * ROWS_STEP] + ws[7 * ROWS_STEP]));
        g_contrib[f * BB + row0 + (STEPS - 1) * ROWS_STEP + tid] = s + b3f;
    }
}

__global__ void finalize_kernel(const float* __restrict__ bias,
                                float* __restrict__ out) {
    int b = blockIdx.x * blockDim.x + threadIdx.x;
    if (b >= BB) return;
    float l = bias[0];
    #pragma unroll 16
    for (int f = 0; f < FF; ++f) l += g_contrib[f * BB + b];
    float p = 1.0f / (1.0f + expf(-l));
    out[2 * b + 0] = 1.0f - p;
    out[2 * b + 1] = p;
}

extern "C" void kernel_launch(void* const* d_in, const int* in_sizes, int n_in,
                              void* d_out, int out_size) {
    const float* x    = (const float*)d_in[0];
    const float* w1   = (const float*)d_in[1];
    const float* b1   = (const float*)d_in[2];
    const float* w2   = (const float*)d_in[3];
    const float* b2   = (const float*)d_in[4];
    const float* w3   = (const float*)d_in[5];
    const float* b3   = (const float*)d_in[6];
    const float* bias = (const float*)d_in[7];
    float* out = (float*)d_out;

    prep_kernel<<<(FF * 2048) / 256, 256>>>(w2);
    dim3 grid(NCHUNK, FF);   // 32 x 128 = 4096 CTAs
    mlp_mma_kernel<<<grid, THREADS>>>(x, w1, b1, b2, w3, b3);
    finalize_kernel<<<BB / 256, 256>>>(bias, out);
}